// round 8
// baseline (speedup 1.0000x reference)
#include <cuda_runtime.h>
#include <cuda_bf16.h>
#include <cstdint>
#include <math.h>

#define D_DIM 1024
#define I_DIM 4096
#define E_NUM 8
#define TOPK  2
#define T_MAX 2048
#define PADR  128
#define NPOS  (T_MAX*TOPK + E_NUM*PADR)   // 5120
#define NROWTILE (NPOS/PADR)              // 40

// ---- smem layouts (pitch 80B per 32-bf16 row; ldmatrix conflict-free) ------
#define STAGE1 40960
#define O1_AH  0
#define O1_AL  10240
#define O1_B1H 20480
#define O1_B1L 25600
#define O1_B3H 30720
#define O1_B3L 35840
#define SMEM1  (512 + 3*STAGE1)           // 123392

#define STAGE2 30720
#define O2_AH  0
#define O2_AL  10240
#define O2_BH  20480
#define O2_BL  25600
#define SMEM2  (512 + 3*STAGE2)           // 92672

// ---------------- scratch ----------------------------------------------------
__device__ int   g_counts[E_NUM];
__device__ int   g_offsets[E_NUM + 1];
__device__ int   g_cursor[E_NUM];
__device__ int   g_tile_expert[NROWTILE];
__device__ int   g_pos_token[NPOS];
__device__ float g_pos_wt[NPOS];
__device__ int   g_slot_pos[T_MAX * TOPK];
__device__ int   g_tok_eidx[T_MAX * TOPK];
__device__ float g_tok_ewt[T_MAX * TOPK];
__device__ __nv_bfloat16 g_hh[(size_t)NPOS * I_DIM];   // ~42 MB
__device__ __nv_bfloat16 g_hl[(size_t)NPOS * I_DIM];   // ~42 MB
__device__ float g_y[(size_t)NPOS * D_DIM];            // ~21 MB

// ---------------- helpers ----------------------------------------------------
__device__ __forceinline__ uint32_t smem_u32(const void* p) {
    uint32_t a;
    asm("{ .reg .u64 t; cvta.to.shared.u64 t, %1; cvt.u32.u64 %0, t; }" : "=r"(a) : "l"(p));
    return a;
}
__device__ __forceinline__ void ldm_x4(uint32_t* r, uint32_t addr) {
    asm volatile("ldmatrix.sync.aligned.m8n8.x4.shared.b16 {%0,%1,%2,%3}, [%4];"
        : "=r"(r[0]), "=r"(r[1]), "=r"(r[2]), "=r"(r[3]) : "r"(addr));
}
__device__ __forceinline__ void mma_bf16(float* c, const uint32_t* a, uint32_t b0, uint32_t b1) {
    asm volatile("mma.sync.aligned.m16n8k16.row.col.f32.bf16.bf16.f32 "
        "{%0,%1,%2,%3}, {%4,%5,%6,%7}, {%8,%9}, {%0,%1,%2,%3};"
        : "+f"(c[0]), "+f"(c[1]), "+f"(c[2]), "+f"(c[3])
        : "r"(a[0]), "r"(a[1]), "r"(a[2]), "r"(a[3]), "r"(b0), "r"(b1));
}
// fp32x4 -> bf16 hi/lo, store 8B each
__device__ __forceinline__ void cvt_store(char* dh, char* dl, float4 v) {
    __nv_bfloat162 h0 = __floats2bfloat162_rn(v.x, v.y);
    __nv_bfloat162 h1 = __floats2bfloat162_rn(v.z, v.w);
    __nv_bfloat162 l0 = __floats2bfloat162_rn(v.x - __bfloat162float(h0.x),
                                              v.y - __bfloat162float(h0.y));
    __nv_bfloat162 l1 = __floats2bfloat162_rn(v.z - __bfloat162float(h1.x),
                                              v.w - __bfloat162float(h1.y));
    *(uint2*)dh = make_uint2(reinterpret_cast<uint32_t&>(h0), reinterpret_cast<uint32_t&>(h1));
    *(uint2*)dl = make_uint2(reinterpret_cast<uint32_t&>(l0), reinterpret_cast<uint32_t&>(l1));
}
__device__ __forceinline__ void split2(float a, float b, uint32_t& h, uint32_t& l) {
    __nv_bfloat162 hh = __floats2bfloat162_rn(a, b);
    __nv_bfloat162 ll = __floats2bfloat162_rn(a - __bfloat162float(hh.x),
                                              b - __bfloat162float(hh.y));
    h = reinterpret_cast<uint32_t&>(hh);
    l = reinterpret_cast<uint32_t&>(ll);
}

// ---------------- small kernels ----------------------------------------------
__global__ void init_kernel() {
    int i = blockIdx.x * blockDim.x + threadIdx.x;
    if (i < E_NUM) g_counts[i] = 0;
    if (i < NPOS) { g_pos_token[i] = -1; g_pos_wt[i] = 0.f; }
}

__global__ void gate_kernel(const float* __restrict__ x,
                            const float* __restrict__ gw, int T) {
    int gtid = blockIdx.x * blockDim.x + threadIdx.x;
    int warp = gtid >> 5, lane = gtid & 31;
    if (warp >= T) return;
    const float* xr = x + (size_t)warp * D_DIM;
    float acc[E_NUM];
#pragma unroll
    for (int e = 0; e < E_NUM; e++) acc[e] = 0.f;
    for (int k = lane; k < D_DIM; k += 32) {
        float xv = xr[k];
#pragma unroll
        for (int e = 0; e < E_NUM; e++)
            acc[e] = fmaf(xv, gw[e * D_DIM + k], acc[e]);
    }
#pragma unroll
    for (int e = 0; e < E_NUM; e++)
#pragma unroll
        for (int off = 16; off > 0; off >>= 1)
            acc[e] += __shfl_down_sync(0xFFFFFFFFu, acc[e], off);
    if (lane == 0) {
        int i0 = 0;
#pragma unroll
        for (int e = 1; e < E_NUM; e++) if (acc[e] > acc[i0]) i0 = e;
        int i1 = (i0 == 0) ? 1 : 0;
#pragma unroll
        for (int e = 0; e < E_NUM; e++)
            if (e != i0 && acc[e] > acc[i1]) i1 = e;
        float m = fmaxf(acc[i0], acc[i1]);
        float p0 = __expf(acc[i0] - m), p1 = __expf(acc[i1] - m);
        float s = p0 + p1;
        int base = warp * TOPK;
        g_tok_eidx[base + 0] = i0; g_tok_ewt[base + 0] = p0 / s;
        g_tok_eidx[base + 1] = i1; g_tok_ewt[base + 1] = p1 / s;
        atomicAdd(&g_counts[i0], 1);
        atomicAdd(&g_counts[i1], 1);
    }
}

__global__ void offsets_kernel() {
    if (threadIdx.x == 0 && blockIdx.x == 0) {
        int total = 0;
        for (int e = 0; e < E_NUM; e++) {
            g_offsets[e] = total;
            g_cursor[e]  = total;
            total += (g_counts[e] + PADR - 1) & ~(PADR - 1);
        }
        g_offsets[E_NUM] = total;
        for (int t = 0; t < NROWTILE; t++) {
            int r0 = t * PADR;
            int e = 0;
            while (e < E_NUM - 1 && r0 >= g_offsets[e + 1]) e++;
            g_tile_expert[t] = (r0 < total) ? e : -1;
        }
    }
}

__global__ void scatter_kernel(int T) {
    int idx = blockIdx.x * blockDim.x + threadIdx.x;
    if (idx >= T * TOPK) return;
    int e = g_tok_eidx[idx];
    int pos = atomicAdd(&g_cursor[e], 1);
    g_pos_token[pos] = idx >> 1;
    g_pos_wt[pos]    = g_tok_ewt[idx];
    g_slot_pos[idx]  = pos;
}

// ---------------- GEMM1: 128x64 tile; warps 0-7: D1, warps 8-15: D3 ----------
__global__ __launch_bounds__(512, 1)
void gemm1_kernel(const float* __restrict__ x,
                  const float* __restrict__ w1,
                  const float* __restrict__ w3) {
    extern __shared__ char sm[];
    int e = g_tile_expert[blockIdx.y];
    if (e < 0) return;
    int tid = threadIdx.x, lane = tid & 31, wid = tid >> 5;
    int r0 = blockIdx.y * PADR, c0 = blockIdx.x * 64;
    int* s_tok = (int*)sm;
    char* tiles = sm + 512;
    uint32_t tiles_u = smem_u32(sm) + 512;

    if (tid < 128) s_tok[tid] = g_pos_token[r0 + tid];
    __syncthreads();

    int wg = wid >> 3;            // 0: D1(w1), 1: D3(w3)
    int wl = wid & 7;
    int mrow = (wl >> 1) * 32;    // 0..96
    int ncol = (wl & 1) * 32;     // 0,32

    float c[2][4][4];
#pragma unroll
    for (int a = 0; a < 2; a++)
#pragma unroll
        for (int b = 0; b < 4; b++)
#pragma unroll
            for (int q = 0; q < 4; q++) c[a][b][q] = 0.f;

    float4 v[4];
    auto load_stage = [&](int kc) {
        int k0 = kc * 32;
#pragma unroll
        for (int it = 0; it < 4; it++) {
            int gid = it * 512 + tid;
            const float* src;
            if (gid < 1024) {
                int r = gid >> 3, c4 = gid & 7;
                int tok = s_tok[r];
                src = (tok >= 0) ? x + (size_t)tok * D_DIM + k0 + c4 * 4 : nullptr;
            } else if (gid < 1536) {
                int g = gid - 1024, r = g >> 3, c4 = g & 7;
                src = w1 + ((size_t)e * I_DIM + c0 + r) * D_DIM + k0 + c4 * 4;
            } else {
                int g = gid - 1536, r = g >> 3, c4 = g & 7;
                src = w3 + ((size_t)e * I_DIM + c0 + r) * D_DIM + k0 + c4 * 4;
            }
            v[it] = src ? *(const float4*)src : make_float4(0.f, 0.f, 0.f, 0.f);
        }
    };
    auto store_stage = [&](int st) {
        char* base = tiles + st * STAGE1;
#pragma unroll
        for (int it = 0; it < 4; it++) {
            int gid = it * 512 + tid;
            int oh, ol, r, c4;
            if (gid < 1024)      { r = gid >> 3;           c4 = gid & 7; oh = O1_AH;  ol = O1_AL;  }
            else if (gid < 1536) { int g = gid - 1024; r = g >> 3; c4 = g & 7; oh = O1_B1H; ol = O1_B1L; }
            else                 { int g = gid - 1536; r = g >> 3; c4 = g & 7; oh = O1_B3H; ol = O1_B3L; }
            int off = r * 80 + c4 * 8;
            cvt_store(base + oh + off, base + ol + off, v[it]);
        }
    };
    auto compute = [&](int st) {
        uint32_t su = tiles_u + st * STAGE1;
#pragma unroll
        for (int kk = 0; kk < 2; kk++) {
            int ko = kk * 32;  // 16 bf16 = 32B
            uint32_t ah[2][4], al[2][4];
#pragma unroll
            for (int mt = 0; mt < 2; mt++) {
                uint32_t aaddr = su + O1_AH
                    + (uint32_t)((mrow + mt * 16 + (lane & 15)) * 80 + ko + (lane >> 4) * 16);
                ldm_x4(ah[mt], aaddr);
                ldm_x4(al[mt], aaddr + (O1_AL - O1_AH));
            }
            uint32_t bbase = su + (wg ? O1_B3H : O1_B1H);
#pragma unroll
            for (int nt2 = 0; nt2 < 2; nt2++) {
                uint32_t bh[4], bl[4];
                uint32_t baddr = bbase
                    + (uint32_t)((ncol + nt2 * 16 + (lane & 15)) * 80 + ko + (lane >> 4) * 16);
                ldm_x4(bh, baddr);
                ldm_x4(bl, baddr + 5120);
#pragma unroll
                for (int mt = 0; mt < 2; mt++)
#pragma unroll
                    for (int sub = 0; sub < 2; sub++) {
                        float* cc = c[mt][nt2 * 2 + sub];
                        mma_bf16(cc, ah[mt], bh[sub], bh[sub + 2]);
                        mma_bf16(cc, al[mt], bh[sub], bh[sub + 2]);
                        mma_bf16(cc, ah[mt], bl[sub], bl[sub + 2]);
                    }
            }
        }
    };

    // triple-buffered pipeline: one sync per chunk
    load_stage(0);
    store_stage(0);
    load_stage(1);
#pragma unroll 1
    for (int kc = 0; kc < 32; kc++) {
        if (kc + 1 < 32) store_stage((kc + 1) % 3);
        if (kc + 2 < 32) load_stage(kc + 2);
        __syncthreads();
        compute(kc % 3);
    }
    __syncthreads();   // protect smem reuse by epilogue exchange

    // epilogue: D3 warps -> smem; D1 warps: h = silu(d1)*d3 -> g_hh/g_hl (bf16)
    float* stg = (float*)(sm + 512);   // [128][68]
    if (wg == 1) {
#pragma unroll
        for (int mt = 0; mt < 2; mt++)
#pragma unroll
            for (int nt = 0; nt < 4; nt++) {
                int row = mrow + mt * 16 + (lane >> 2);
                int col = ncol + nt * 8 + 2 * (lane & 3);
                float* cc = c[mt][nt];
                *(float2*)&stg[row * 68 + col]       = make_float2(cc[0], cc[1]);
                *(float2*)&stg[(row + 8) * 68 + col] = make_float2(cc[2], cc[3]);
            }
    }
    __syncthreads();
    if (wg == 0) {
#pragma unroll
        for (int mt = 0; mt < 2; mt++)
#pragma unroll
            for (int nt = 0; nt < 4; nt++) {
                int row = mrow + mt * 16 + (lane >> 2);
                int col = ncol + nt * 8 + 2 * (lane & 3);
                float* cc = c[mt][nt];
                float2 d3a = *(float2*)&stg[row * 68 + col];
                float2 d3b = *(float2*)&stg[(row + 8) * 68 + col];
                float h0 = cc[0] * d3a.x / (1.f + __expf(-cc[0]));
                float h1 = cc[1] * d3a.y / (1.f + __expf(-cc[1]));
                float h2 = cc[2] * d3b.x / (1.f + __expf(-cc[2]));
                float h3 = cc[3] * d3b.y / (1.f + __expf(-cc[3]));
                uint32_t ha, la, hb, lb;
                split2(h0, h1, ha, la);
                split2(h2, h3, hb, lb);
                size_t o0 = (size_t)(r0 + row) * I_DIM + c0 + col;
                size_t o1 = (size_t)(r0 + row + 8) * I_DIM + c0 + col;
                *(uint32_t*)(g_hh + o0) = ha;
                *(uint32_t*)(g_hl + o0) = la;
                *(uint32_t*)(g_hh + o1) = hb;
                *(uint32_t*)(g_hl + o1) = lb;
            }
    }
}

// ---------------- GEMM2: 128x64 tile; warp m32n16; y = (h·w2ᵀ)*wt ------------
__global__ __launch_bounds__(512, 1)
void gemm2_kernel(const float* __restrict__ w2) {
    extern __shared__ char sm[];
    int e = g_tile_expert[blockIdx.y];
    if (e < 0) return;
    int tid = threadIdx.x, lane = tid & 31, wid = tid >> 5;
    int r0 = blockIdx.y * PADR, c0 = blockIdx.x * 64;
    char* tiles = sm + 512;
    uint32_t tiles_u = smem_u32(sm) + 512;

    int mrow = (wid >> 2) * 32;   // 0..96
    int ncol = (wid & 3) * 16;    // 0..48

    float c[2][2][4];
#pragma unroll
    for (int a = 0; a < 2; a++)
#pragma unroll
        for (int b = 0; b < 2; b++)
#pragma unroll
            for (int q = 0; q < 4; q++) c[a][b][q] = 0.f;

    uint4 va0, va1;
    float4 vb;
    int arow = tid >> 2, ach = tid & 3;      // A: 128 rows x 4 16B-chunks
    int brow = tid >> 3, bc4 = tid & 7;      // B: 64 rows x 8 float4

    auto load_stage = [&](int kc) {
        int k0 = kc * 32;
        const char* ph = (const char*)(g_hh + (size_t)(r0 + arow) * I_DIM + k0);
        const char* pl = (const char*)(g_hl + (size_t)(r0 + arow) * I_DIM + k0);
        va0 = *(const uint4*)(ph + ach * 16);
        va1 = *(const uint4*)(pl + ach * 16);
        vb  = *(const float4*)(w2 + ((size_t)e * D_DIM + c0 + brow) * I_DIM + k0 + bc4 * 4);
    };
    auto store_stage = [&](int st) {
        char* base = tiles + st * STAGE2;
        int aoff = arow * 80 + ach * 16;
        *(uint4*)(base + O2_AH + aoff) = va0;
        *(uint4*)(base + O2_AL + aoff) = va1;
        int boff = brow * 80 + bc4 * 8;
        cvt_store(base + O2_BH + boff, base + O2_BL + boff, vb);
    };
    auto compute = [&](int st) {
        uint32_t su = tiles_u + st * STAGE2;
#pragma unroll
        for (int kk = 0; kk < 2; kk++) {
            int ko = kk * 32;
            uint32_t ah[2][4], al[2][4];
#pragma unroll
            for (int mt = 0; mt < 2; mt++) {
                uint32_t aaddr = su + O2_AH
                    + (uint32_t)((mrow + mt * 16 + (lane & 15)) * 80 + ko + (lane >> 4) * 16);
                ldm_x4(ah[mt], aaddr);
                ldm_x4(al[mt], aaddr + (O2_AL - O2_AH));
            }
            uint32_t bh[4], bl[4];
            uint32_t baddr = su + O2_BH
                + (uint32_t)((ncol + (lane & 15)) * 80 + ko + (lane >> 4) * 16);
            ldm_x4(bh, baddr);
            ldm_x4(bl, baddr + (O2_BL - O2_BH));
#pragma unroll
            for (int mt = 0; mt < 2; mt++)
#pragma unroll
                for (int sub = 0; sub < 2; sub++) {
                    float* cc = c[mt][sub];
                    mma_bf16(cc, ah[mt], bh[sub], bh[sub + 2]);
                    mma_bf16(cc, al[mt], bh[sub], bh[sub + 2]);
                    mma_bf16(cc, ah[mt], bl[sub], bl[sub + 2]);
                }
        }
    };

    load_stage(0);
    store_stage(0);
    load_stage(1);
#pragma unroll 1
    for (int kc = 0; kc < 128; kc++) {
        if (kc + 1 < 128) store_stage((kc + 1) % 3);
        if (kc + 2 < 128) load_stage(kc + 2);
        __syncthreads();
        compute(kc % 3);
    }

#pragma unroll
    for (int mt = 0; mt < 2; mt++) {
        int row = mrow + mt * 16 + (lane >> 2);
        float wa = g_pos_wt[r0 + row];
        float wb = g_pos_wt[r0 + row + 8];
#pragma unroll
        for (int nt = 0; nt < 2; nt++) {
            int col = ncol + nt * 8 + 2 * (lane & 3);
            float* cc = c[mt][nt];
            *(float2*)(g_y + (size_t)(r0 + row) * D_DIM + c0 + col)
                = make_float2(cc[0] * wa, cc[1] * wa);
            *(float2*)(g_y + (size_t)(r0 + row + 8) * D_DIM + c0 + col)
                = make_float2(cc[2] * wb, cc[3] * wb);
        }
    }
}

// ---------------- combine ----------------------------------------------------
__global__ void combine_kernel(float* __restrict__ out, int T) {
    int idx = blockIdx.x * blockDim.x + threadIdx.x;
    int total = T * (D_DIM / 4);
    if (idx >= total) return;
    int t = idx / (D_DIM / 4);
    int d4 = idx - t * (D_DIM / 4);
    int p0 = g_slot_pos[2 * t];
    int p1 = g_slot_pos[2 * t + 1];
    const float4* y0 = (const float4*)(g_y + (size_t)p0 * D_DIM) + d4;
    const float4* y1 = (const float4*)(g_y + (size_t)p1 * D_DIM) + d4;
    float4 a = *y0, b = *y1;
    float4 r;
    r.x = a.x + b.x; r.y = a.y + b.y; r.z = a.z + b.z; r.w = a.w + b.w;
    ((float4*)out)[idx] = r;
}

// ---------------- launch -----------------------------------------------------
extern "C" void kernel_launch(void* const* d_in, const int* in_sizes, int n_in,
                              void* d_out, int out_size) {
    const float* x  = (const float*)d_in[0];
    const float* gw = (const float*)d_in[1];
    const float* w1 = (const float*)d_in[2];
    const float* w2 = (const float*)d_in[3];
    const float* w3 = (const float*)d_in[4];
    float* out = (float*)d_out;

    int T = in_sizes[0] / D_DIM;
    if (T > T_MAX) T = T_MAX;

    cudaFuncSetAttribute(gemm1_kernel, cudaFuncAttributeMaxDynamicSharedMemorySize, SMEM1);
    cudaFuncSetAttribute(gemm2_kernel, cudaFuncAttributeMaxDynamicSharedMemorySize, SMEM2);

    init_kernel<<<(NPOS + 255) / 256, 256>>>();
    gate_kernel<<<(T * 32 + 255) / 256, 256>>>(x, gw, T);
    offsets_kernel<<<1, 32>>>();
    scatter_kernel<<<(T * TOPK + 255) / 256, 256>>>(T);

    dim3 grid1(I_DIM / 64, NROWTILE);
    gemm1_kernel<<<grid1, 512, SMEM1>>>(x, w1, w3);

    dim3 grid2(D_DIM / 64, NROWTILE);
    gemm2_kernel<<<grid2, 512, SMEM2>>>(w2);

    combine_kernel<<<(T * (D_DIM / 4) + 255) / 256, 256>>>(out, T);
}

// round 9
// speedup vs baseline: 1.0784x; 1.0784x over previous
#include <cuda_runtime.h>
#include <cuda_bf16.h>
#include <cstdint>
#include <math.h>

#define D_DIM 1024
#define I_DIM 4096
#define E_NUM 8
#define TOPK  2
#define T_MAX 2048
#define PADR  128
#define NPOS  (T_MAX*TOPK + E_NUM*PADR)   // 5120
#define NROWTILE (NPOS/PADR)              // 40

// ---- GEMM1 stage: A(x) 128r hi/lo + B1 64r hi/lo + B3 64r hi/lo, 80B pitch --
#define STAGE1 40960
#define O1_AH  0
#define O1_AL  10240
#define O1_B1H 20480
#define O1_B1L 25600
#define O1_B3H 30720
#define O1_B3L 35840
#define SMEM1  (512 + 2*STAGE1)           // 82432, 2 CTAs/SM

// ---- GEMM2 stage: A(h) 128r hi/lo + B(w2) 64r hi/lo ------------------------
#define STAGE2 30720
#define O2_AH  0
#define O2_AL  10240
#define O2_BH  20480
#define O2_BL  25600
#define SMEM2  (3*STAGE2)                 // 92160, 2 CTAs/SM

// ---------------- scratch ----------------------------------------------------
__device__ int   g_counts[E_NUM];
__device__ int   g_offsets[E_NUM + 1];
__device__ int   g_cursor[E_NUM];
__device__ int   g_tile_expert[NROWTILE];
__device__ int   g_pos_token[NPOS];
__device__ float g_pos_wt[NPOS];
__device__ int   g_slot_pos[T_MAX * TOPK];
__device__ int   g_tok_eidx[T_MAX * TOPK];
__device__ float g_tok_ewt[T_MAX * TOPK];

__device__ __nv_bfloat16 g_xh[(size_t)T_MAX * D_DIM];
__device__ __nv_bfloat16 g_xl[(size_t)T_MAX * D_DIM];
__device__ __nv_bfloat16 g_w1h[(size_t)E_NUM * I_DIM * D_DIM];
__device__ __nv_bfloat16 g_w1l[(size_t)E_NUM * I_DIM * D_DIM];
__device__ __nv_bfloat16 g_w3h[(size_t)E_NUM * I_DIM * D_DIM];
__device__ __nv_bfloat16 g_w3l[(size_t)E_NUM * I_DIM * D_DIM];
__device__ __nv_bfloat16 g_w2h[(size_t)E_NUM * D_DIM * I_DIM];
__device__ __nv_bfloat16 g_w2l[(size_t)E_NUM * D_DIM * I_DIM];
__device__ __nv_bfloat16 g_hh[(size_t)NPOS * I_DIM];
__device__ __nv_bfloat16 g_hl[(size_t)NPOS * I_DIM];
__device__ float g_y[(size_t)NPOS * D_DIM];

// ---------------- helpers ----------------------------------------------------
__device__ __forceinline__ uint32_t smem_u32(const void* p) {
    uint32_t a;
    asm("{ .reg .u64 t; cvta.to.shared.u64 t, %1; cvt.u32.u64 %0, t; }" : "=r"(a) : "l"(p));
    return a;
}
__device__ __forceinline__ void ldm_x4(uint32_t* r, uint32_t addr) {
    asm volatile("ldmatrix.sync.aligned.m8n8.x4.shared.b16 {%0,%1,%2,%3}, [%4];"
        : "=r"(r[0]), "=r"(r[1]), "=r"(r[2]), "=r"(r[3]) : "r"(addr));
}
__device__ __forceinline__ void mma_bf16(float* c, const uint32_t* a, uint32_t b0, uint32_t b1) {
    asm volatile("mma.sync.aligned.m16n8k16.row.col.f32.bf16.bf16.f32 "
        "{%0,%1,%2,%3}, {%4,%5,%6,%7}, {%8,%9}, {%0,%1,%2,%3};"
        : "+f"(c[0]), "+f"(c[1]), "+f"(c[2]), "+f"(c[3])
        : "r"(a[0]), "r"(a[1]), "r"(a[2]), "r"(a[3]), "r"(b0), "r"(b1));
}
__device__ __forceinline__ void cp16(uint32_t dst, const void* src) {
    asm volatile("cp.async.cg.shared.global [%0], [%1], 16;" :: "r"(dst), "l"(src) : "memory");
}
__device__ __forceinline__ void cp16z(uint32_t dst, const void* src, int nbytes) {
    asm volatile("cp.async.cg.shared.global [%0], [%1], 16, %2;"
        :: "r"(dst), "l"(src), "r"(nbytes) : "memory");
}
__device__ __forceinline__ void cp_commit() {
    asm volatile("cp.async.commit_group;" ::: "memory");
}
template <int N>
__device__ __forceinline__ void cp_wait() {
    asm volatile("cp.async.wait_group %0;" :: "n"(N) : "memory");
}
__device__ __forceinline__ void split2(float a, float b, uint32_t& h, uint32_t& l) {
    __nv_bfloat162 hh = __floats2bfloat162_rn(a, b);
    __nv_bfloat162 ll = __floats2bfloat162_rn(a - __bfloat162float(hh.x),
                                              b - __bfloat162float(hh.y));
    h = reinterpret_cast<uint32_t&>(hh);
    l = reinterpret_cast<uint32_t&>(ll);
}

// ---------------- small kernels ----------------------------------------------
__global__ void init_kernel() {
    int i = blockIdx.x * blockDim.x + threadIdx.x;
    if (i < E_NUM) g_counts[i] = 0;
    if (i < NPOS) { g_pos_token[i] = -1; g_pos_wt[i] = 0.f; }
}

__global__ void split_kernel(const float* __restrict__ src,
                             __nv_bfloat16* __restrict__ hi,
                             __nv_bfloat16* __restrict__ lo, int n4) {
    int i = blockIdx.x * blockDim.x + threadIdx.x;
    if (i >= n4) return;
    float4 v = ((const float4*)src)[i];
    uint32_t h0, l0, h1, l1;
    split2(v.x, v.y, h0, l0);
    split2(v.z, v.w, h1, l1);
    ((uint2*)hi)[i] = make_uint2(h0, h1);
    ((uint2*)lo)[i] = make_uint2(l0, l1);
}

__global__ void gate_kernel(const float* __restrict__ x,
                            const float* __restrict__ gw, int T) {
    int gtid = blockIdx.x * blockDim.x + threadIdx.x;
    int warp = gtid >> 5, lane = gtid & 31;
    if (warp >= T) return;
    const float* xr = x + (size_t)warp * D_DIM;
    float acc[E_NUM];
#pragma unroll
    for (int e = 0; e < E_NUM; e++) acc[e] = 0.f;
    for (int k = lane; k < D_DIM; k += 32) {
        float xv = xr[k];
#pragma unroll
        for (int e = 0; e < E_NUM; e++)
            acc[e] = fmaf(xv, gw[e * D_DIM + k], acc[e]);
    }
#pragma unroll
    for (int e = 0; e < E_NUM; e++)
#pragma unroll
        for (int off = 16; off > 0; off >>= 1)
            acc[e] += __shfl_down_sync(0xFFFFFFFFu, acc[e], off);
    if (lane == 0) {
        int i0 = 0;
#pragma unroll
        for (int e = 1; e < E_NUM; e++) if (acc[e] > acc[i0]) i0 = e;
        int i1 = (i0 == 0) ? 1 : 0;
#pragma unroll
        for (int e = 0; e < E_NUM; e++)
            if (e != i0 && acc[e] > acc[i1]) i1 = e;
        float m = fmaxf(acc[i0], acc[i1]);
        float p0 = __expf(acc[i0] - m), p1 = __expf(acc[i1] - m);
        float s = p0 + p1;
        int base = warp * TOPK;
        g_tok_eidx[base + 0] = i0; g_tok_ewt[base + 0] = p0 / s;
        g_tok_eidx[base + 1] = i1; g_tok_ewt[base + 1] = p1 / s;
        atomicAdd(&g_counts[i0], 1);
        atomicAdd(&g_counts[i1], 1);
    }
}

__global__ void offsets_kernel() {
    if (threadIdx.x == 0 && blockIdx.x == 0) {
        int total = 0;
        for (int e = 0; e < E_NUM; e++) {
            g_offsets[e] = total;
            g_cursor[e]  = total;
            total += (g_counts[e] + PADR - 1) & ~(PADR - 1);
        }
        g_offsets[E_NUM] = total;
        for (int t = 0; t < NROWTILE; t++) {
            int r0 = t * PADR;
            int e = 0;
            while (e < E_NUM - 1 && r0 >= g_offsets[e + 1]) e++;
            g_tile_expert[t] = (r0 < total) ? e : -1;
        }
    }
}

__global__ void scatter_kernel(int T) {
    int idx = blockIdx.x * blockDim.x + threadIdx.x;
    if (idx >= T * TOPK) return;
    int e = g_tok_eidx[idx];
    int pos = atomicAdd(&g_cursor[e], 1);
    g_pos_token[pos] = idx >> 1;
    g_pos_wt[pos]    = g_tok_ewt[idx];
    g_slot_pos[idx]  = pos;
}

// ---------------- GEMM1: CTA 128x64, 8 warps, warp m32xn32 computes D1 AND D3
__global__ __launch_bounds__(256, 2)
void gemm1_kernel() {
    extern __shared__ __align__(128) char sm[];
    int e = g_tile_expert[blockIdx.y];
    if (e < 0) return;
    int tid = threadIdx.x, lane = tid & 31, wid = tid >> 5;
    int r0 = blockIdx.y * PADR, c0 = blockIdx.x * 64;
    int* s_tok = (int*)sm;
    uint32_t tiles_u = smem_u32(sm) + 512;

    if (tid < 128) s_tok[tid] = g_pos_token[r0 + tid];
    __syncthreads();

    int mrow = (wid >> 1) * 32;   // 0,32,64,96
    int ncol = (wid & 1) * 32;    // 0,32

    float c1[2][4][4], c3[2][4][4];
#pragma unroll
    for (int a = 0; a < 2; a++)
#pragma unroll
        for (int b = 0; b < 4; b++)
#pragma unroll
            for (int q = 0; q < 4; q++) { c1[a][b][q] = 0.f; c3[a][b][q] = 0.f; }

    auto issue_stage = [&](int kc, int st) {
        uint32_t base = tiles_u + st * STAGE1;
        int kb = kc * 32;   // bf16 offset
#pragma unroll
        for (int it = 0; it < 8; it++) {
            int gid = it * 256 + tid;
            if (gid < 1024) {
                int hl = gid >> 9, r = (gid >> 2) & 127, cc = gid & 3;
                int tok = s_tok[r];
                const __nv_bfloat16* bp = hl ? g_xl : g_xh;
                const __nv_bfloat16* sp = bp
                    + ((size_t)(tok >= 0 ? tok : 0) * D_DIM + kb + cc * 8);
                cp16z(base + (hl ? O1_AL : O1_AH) + r * 80 + cc * 16, sp,
                      tok >= 0 ? 16 : 0);
            } else {
                int g2 = gid - 1024;
                int is3 = g2 >> 9;
                int g3 = g2 & 511;
                int hl = g3 >> 8, r = (g3 >> 2) & 63, cc = g3 & 3;
                const __nv_bfloat16* wp = is3 ? (hl ? g_w3l : g_w3h)
                                              : (hl ? g_w1l : g_w1h);
                const __nv_bfloat16* sp = wp
                    + (((size_t)e * I_DIM + c0 + r) * D_DIM + kb + cc * 8);
                uint32_t off = (is3 ? O1_B3H : O1_B1H) + (hl ? 5120u : 0u)
                             + r * 80 + cc * 16;
                cp16(base + off, sp);
            }
        }
    };

    auto compute = [&](int st) {
        uint32_t su = tiles_u + st * STAGE1;
#pragma unroll
        for (int kk = 0; kk < 2; kk++) {
            int ko = kk * 32;
            uint32_t ah[2][4], al[2][4];
#pragma unroll
            for (int mt = 0; mt < 2; mt++) {
                uint32_t aaddr = su
                    + (uint32_t)((mrow + mt * 16 + (lane & 15)) * 80 + ko + (lane >> 4) * 16);
                ldm_x4(ah[mt], aaddr);
                ldm_x4(al[mt], aaddr + 10240);
            }
#pragma unroll
            for (int nt = 0; nt < 2; nt++) {
                uint32_t b1h[4], b1l[4], b3h[4], b3l[4];
                uint32_t baddr = su + O1_B1H
                    + (uint32_t)((ncol + nt * 16 + (lane & 15)) * 80 + ko + (lane >> 4) * 16);
                ldm_x4(b1h, baddr);
                ldm_x4(b1l, baddr + 5120);
                ldm_x4(b3h, baddr + 10240);
                ldm_x4(b3l, baddr + 15360);
#pragma unroll
                for (int mt = 0; mt < 2; mt++)
#pragma unroll
                    for (int sub = 0; sub < 2; sub++) {
                        float* cc1 = c1[mt][nt * 2 + sub];
                        mma_bf16(cc1, ah[mt], b1h[sub], b1h[sub + 2]);
                        mma_bf16(cc1, al[mt], b1h[sub], b1h[sub + 2]);
                        mma_bf16(cc1, ah[mt], b1l[sub], b1l[sub + 2]);
                        float* cc3 = c3[mt][nt * 2 + sub];
                        mma_bf16(cc3, ah[mt], b3h[sub], b3h[sub + 2]);
                        mma_bf16(cc3, al[mt], b3h[sub], b3h[sub + 2]);
                        mma_bf16(cc3, ah[mt], b3l[sub], b3l[sub + 2]);
                    }
            }
        }
    };

    issue_stage(0, 0); cp_commit();
    issue_stage(1, 1); cp_commit();
#pragma unroll 1
    for (int kc = 0; kc < 32; kc++) {
        if (kc < 31) cp_wait<1>(); else cp_wait<0>();
        __syncthreads();
        compute(kc & 1);
        __syncthreads();
        if (kc + 2 < 32) { issue_stage(kc + 2, kc & 1); cp_commit(); }
    }

    // epilogue: both accumulators in-warp — no exchange
#pragma unroll
    for (int mt = 0; mt < 2; mt++)
#pragma unroll
        for (int ns = 0; ns < 4; ns++) {
            int row = mrow + mt * 16 + (lane >> 2);
            int col = c0 + ncol + ns * 8 + 2 * (lane & 3);
            float* a1 = c1[mt][ns];
            float* a3 = c3[mt][ns];
            float v0 = a1[0] * a3[0] / (1.f + __expf(-a1[0]));
            float v1 = a1[1] * a3[1] / (1.f + __expf(-a1[1]));
            float v2 = a1[2] * a3[2] / (1.f + __expf(-a1[2]));
            float v3 = a1[3] * a3[3] / (1.f + __expf(-a1[3]));
            uint32_t ha, la, hb, lb;
            split2(v0, v1, ha, la);
            split2(v2, v3, hb, lb);
            size_t o0 = (size_t)(r0 + row) * I_DIM + col;
            size_t o1 = (size_t)(r0 + row + 8) * I_DIM + col;
            *(uint32_t*)(g_hh + o0) = ha;
            *(uint32_t*)(g_hl + o0) = la;
            *(uint32_t*)(g_hh + o1) = hb;
            *(uint32_t*)(g_hl + o1) = lb;
        }
}

// ---------------- GEMM2: CTA 128x64, 8 warps, warp m32xn32; y = (h·w2ᵀ)*wt ---
__global__ __launch_bounds__(256, 2)
void gemm2_kernel() {
    extern __shared__ __align__(128) char sm[];
    int e = g_tile_expert[blockIdx.y];
    if (e < 0) return;
    int tid = threadIdx.x, lane = tid & 31, wid = tid >> 5;
    int r0 = blockIdx.y * PADR, c0 = blockIdx.x * 64;
    uint32_t tiles_u = smem_u32(sm);

    int mrow = (wid >> 1) * 32;
    int ncol = (wid & 1) * 32;

    float c[2][4][4];
#pragma unroll
    for (int a = 0; a < 2; a++)
#pragma unroll
        for (int b = 0; b < 4; b++)
#pragma unroll
            for (int q = 0; q < 4; q++) c[a][b][q] = 0.f;

    auto issue_stage = [&](int kc, int st) {
        uint32_t base = tiles_u + st * STAGE2;
        int kb = kc * 32;
#pragma unroll
        for (int it = 0; it < 6; it++) {
            int gid = it * 256 + tid;
            if (gid < 1024) {
                int hl = gid >> 9, r = (gid >> 2) & 127, cc = gid & 3;
                const __nv_bfloat16* bp = hl ? g_hl : g_hh;
                const __nv_bfloat16* sp = bp
                    + ((size_t)(r0 + r) * I_DIM + kb + cc * 8);
                cp16(base + (hl ? O2_AL : O2_AH) + r * 80 + cc * 16, sp);
            } else {
                int g2 = gid - 1024;
                int hl = g2 >> 8, r = (g2 >> 2) & 63, cc = g2 & 3;
                const __nv_bfloat16* wp = hl ? g_w2l : g_w2h;
                const __nv_bfloat16* sp = wp
                    + (((size_t)e * D_DIM + c0 + r) * I_DIM + kb + cc * 8);
                cp16(base + (hl ? O2_BL : O2_BH) + r * 80 + cc * 16, sp);
            }
        }
    };

    auto compute = [&](int st) {
        uint32_t su = tiles_u + st * STAGE2;
#pragma unroll
        for (int kk = 0; kk < 2; kk++) {
            int ko = kk * 32;
            uint32_t ah[2][4], al[2][4];
#pragma unroll
            for (int mt = 0; mt < 2; mt++) {
                uint32_t aaddr = su
                    + (uint32_t)((mrow + mt * 16 + (lane & 15)) * 80 + ko + (lane >> 4) * 16);
                ldm_x4(ah[mt], aaddr);
                ldm_x4(al[mt], aaddr + 10240);
            }
#pragma unroll
            for (int nt = 0; nt < 2; nt++) {
                uint32_t bh[4], bl[4];
                uint32_t baddr = su + O2_BH
                    + (uint32_t)((ncol + nt * 16 + (lane & 15)) * 80 + ko + (lane >> 4) * 16);
                ldm_x4(bh, baddr);
                ldm_x4(bl, baddr + 5120);
#pragma unroll
                for (int mt = 0; mt < 2; mt++)
#pragma unroll
                    for (int sub = 0; sub < 2; sub++) {
                        float* cc = c[mt][nt * 2 + sub];
                        mma_bf16(cc, ah[mt], bh[sub], bh[sub + 2]);
                        mma_bf16(cc, al[mt], bh[sub], bh[sub + 2]);
                        mma_bf16(cc, ah[mt], bl[sub], bl[sub + 2]);
                    }
            }
        }
    };

    issue_stage(0, 0); cp_commit();
    issue_stage(1, 1); cp_commit();
#pragma unroll 1
    for (int kc = 0; kc < 128; kc++) {
        if (kc < 127) cp_wait<1>(); else cp_wait<0>();
        __syncthreads();
        // buffer (kc+2)%3 held stage kc-1; all warps passed the sync after
        // computing it, so overwriting now is race-free (single sync/iter)
        if (kc + 2 < 128) { issue_stage(kc + 2, (kc + 2) % 3); cp_commit(); }
        compute(kc % 3);
    }

#pragma unroll
    for (int mt = 0; mt < 2; mt++) {
        int row = mrow + mt * 16 + (lane >> 2);
        float wa = g_pos_wt[r0 + row];
        float wb = g_pos_wt[r0 + row + 8];
#pragma unroll
        for (int ns = 0; ns < 4; ns++) {
            int col = c0 + ncol + ns * 8 + 2 * (lane & 3);
            float* cc = c[mt][ns];
            *(float2*)(g_y + (size_t)(r0 + row) * D_DIM + col)
                = make_float2(cc[0] * wa, cc[1] * wa);
            *(float2*)(g_y + (size_t)(r0 + row + 8) * D_DIM + col)
                = make_float2(cc[2] * wb, cc[3] * wb);
        }
    }
}

// ---------------- combine ----------------------------------------------------
__global__ void combine_kernel(float* __restrict__ out, int T) {
    int idx = blockIdx.x * blockDim.x + threadIdx.x;
    int total = T * (D_DIM / 4);
    if (idx >= total) return;
    int t = idx / (D_DIM / 4);
    int d4 = idx - t * (D_DIM / 4);
    int p0 = g_slot_pos[2 * t];
    int p1 = g_slot_pos[2 * t + 1];
    const float4* y0 = (const float4*)(g_y + (size_t)p0 * D_DIM) + d4;
    const float4* y1 = (const float4*)(g_y + (size_t)p1 * D_DIM) + d4;
    float4 a = *y0, b = *y1;
    float4 r;
    r.x = a.x + b.x; r.y = a.y + b.y; r.z = a.z + b.z; r.w = a.w + b.w;
    ((float4*)out)[idx] = r;
}

// ---------------- launch -----------------------------------------------------
extern "C" void kernel_launch(void* const* d_in, const int* in_sizes, int n_in,
                              void* d_out, int out_size) {
    const float* x  = (const float*)d_in[0];
    const float* gw = (const float*)d_in[1];
    const float* w1 = (const float*)d_in[2];
    const float* w2 = (const float*)d_in[3];
    const float* w3 = (const float*)d_in[4];
    float* out = (float*)d_out;

    int T = in_sizes[0] / D_DIM;
    if (T > T_MAX) T = T_MAX;

    cudaFuncSetAttribute(gemm1_kernel, cudaFuncAttributeMaxDynamicSharedMemorySize, SMEM1);
    cudaFuncSetAttribute(gemm2_kernel, cudaFuncAttributeMaxDynamicSharedMemorySize, SMEM2);

    init_kernel<<<(NPOS + 255) / 256, 256>>>();
    gate_kernel<<<(T * 32 + 255) / 256, 256>>>(x, gw, T);
    offsets_kernel<<<1, 32>>>();
    scatter_kernel<<<(T * TOPK + 255) / 256, 256>>>(T);

    // one-time fp32 -> bf16 hi/lo pre-splits (x + weights)
    {
        __nv_bfloat16 *xh, *xl, *w1h, *w1l, *w3h, *w3l, *w2h, *w2l;
        cudaGetSymbolAddress((void**)&xh,  g_xh);
        cudaGetSymbolAddress((void**)&xl,  g_xl);
        cudaGetSymbolAddress((void**)&w1h, g_w1h);
        cudaGetSymbolAddress((void**)&w1l, g_w1l);
        cudaGetSymbolAddress((void**)&w3h, g_w3h);
        cudaGetSymbolAddress((void**)&w3l, g_w3l);
        cudaGetSymbolAddress((void**)&w2h, g_w2h);
        cudaGetSymbolAddress((void**)&w2l, g_w2l);
        int nx4 = T * D_DIM / 4;
        int nw4 = E_NUM * I_DIM * D_DIM / 4;
        split_kernel<<<(nx4 + 255) / 256, 256>>>(x, xh, xl, nx4);
        split_kernel<<<(nw4 + 255) / 256, 256>>>(w1, w1h, w1l, nw4);
        split_kernel<<<(nw4 + 255) / 256, 256>>>(w3, w3h, w3l, nw4);
        split_kernel<<<(nw4 + 255) / 256, 256>>>(w2, w2h, w2l, nw4);
    }

    dim3 grid1(I_DIM / 64, NROWTILE);
    gemm1_kernel<<<grid1, 256, SMEM1>>>();

    dim3 grid2(D_DIM / 64, NROWTILE);
    gemm2_kernel<<<grid2, 256, SMEM2>>>();

    combine_kernel<<<(T * (D_DIM / 4) + 255) / 256, 256>>>(out, T);
}